// round 1
// baseline (speedup 1.0000x reference)
#include <cuda_runtime.h>

// BalancedLoss: loss = mean( BCEWithLogits(pred, target) * weights )
// where weights per element are w1[c] (t==1) or w0[c] (t==0), derived from
// per-column pos counts. Single fused pass over pred+target (256 MB), then
// tiny finalize. HBM-bound.

#define CCOLS 512
#define C4 (CCOLS / 4)   // 128 float4 groups per row

// Persistent scratch (allocation-free rule): per-column accumulators.
__device__ float g_accA[CCOLS];  // sum softplus(x) * (1 - t)
__device__ float g_accB[CCOLS];  // sum (softplus(x) - x) * t
__device__ float g_accP[CCOLS];  // sum t  (positive count)

__global__ void bl_zero_kernel() {
    int i = threadIdx.x;
    g_accA[i] = 0.0f;
    g_accB[i] = 0.0f;
    g_accP[i] = 0.0f;
}

__device__ __forceinline__ float softplus_f(float x) {
    // logaddexp(0, x) = max(x,0) + log1p(exp(-|x|)); fast intrinsics are
    // far inside the 1e-3 tolerance.
    return fmaxf(x, 0.0f) + __logf(1.0f + __expf(-fabsf(x)));
}

__global__ __launch_bounds__(512, 2)
void bl_pass1_kernel(const float4* __restrict__ pred,
                     const float4* __restrict__ targ,
                     int Bn) {
    const int tid   = threadIdx.x;          // 0..511
    const int cg    = tid & (C4 - 1);       // column group 0..127 (cols 4*cg..4*cg+3)
    const int rlane = tid >> 7;             // 0..3 (row lane within block)
    const int rowsPerBlock = blockDim.x >> 7;           // 4
    int r = blockIdx.x * rowsPerBlock + rlane;
    const int rstride = gridDim.x * rowsPerBlock;

    float a0 = 0.f, a1 = 0.f, a2 = 0.f, a3 = 0.f;
    float b0 = 0.f, b1 = 0.f, b2 = 0.f, b3 = 0.f;
    float p0 = 0.f, p1 = 0.f, p2 = 0.f, p3 = 0.f;

    #pragma unroll 4
    for (; r < Bn; r += rstride) {
        const int idx = r * C4 + cg;        // <= 8.4M, fits int
        const float4 x = pred[idx];
        const float4 t = targ[idx];

        float s;
        s = softplus_f(x.x);
        a0 += s - s * t.x;  b0 += (s - x.x) * t.x;  p0 += t.x;
        s = softplus_f(x.y);
        a1 += s - s * t.y;  b1 += (s - x.y) * t.y;  p1 += t.y;
        s = softplus_f(x.z);
        a2 += s - s * t.z;  b2 += (s - x.z) * t.z;  p2 += t.z;
        s = softplus_f(x.w);
        a3 += s - s * t.w;  b3 += (s - x.w) * t.w;  p3 += t.w;
    }

    const int c = cg * 4;
    atomicAdd(&g_accA[c + 0], a0);
    atomicAdd(&g_accA[c + 1], a1);
    atomicAdd(&g_accA[c + 2], a2);
    atomicAdd(&g_accA[c + 3], a3);
    atomicAdd(&g_accB[c + 0], b0);
    atomicAdd(&g_accB[c + 1], b1);
    atomicAdd(&g_accB[c + 2], b2);
    atomicAdd(&g_accB[c + 3], b3);
    atomicAdd(&g_accP[c + 0], p0);
    atomicAdd(&g_accP[c + 1], p1);
    atomicAdd(&g_accP[c + 2], p2);
    atomicAdd(&g_accP[c + 3], p3);
}

__global__ void bl_finalize_kernel(const float* __restrict__ pos_prop,
                                   float* __restrict__ out,
                                   int Bn) {
    const int c = threadIdx.x;              // 0..511
    const float Bf = (float)Bn;
    const float P  = g_accP[c];
    const float bn = pos_prop[c] * Bf;      // balance_num

    const bool  majIs1 = (P >= bn);
    const float n_maj  = majIs1 ? P : (Bf - P);
    const float n_min  = Bf - n_maj;
    const float w_maj  = bn / n_maj;
    const float w_min  = (n_min > 0.0f) ? (Bf - bn) / fmaxf(n_min, 1.0f) : 1.0f;
    const float w1 = majIs1 ? w_maj : w_min;   // weight where t == 1
    const float w0 = majIs1 ? w_min : w_maj;   // weight where t == 0

    float contrib = w0 * g_accA[c] + w1 * g_accB[c];

    __shared__ float sh[CCOLS];
    sh[c] = contrib;
    __syncthreads();
    #pragma unroll
    for (int s = CCOLS / 2; s > 0; s >>= 1) {
        if (c < s) sh[c] += sh[c + s];
        __syncthreads();
    }
    if (c == 0) out[0] = sh[0] / (Bf * (float)CCOLS);
}

extern "C" void kernel_launch(void* const* d_in, const int* in_sizes, int n_in,
                              void* d_out, int out_size) {
    const float* pred = (const float*)d_in[0];
    const float* targ = (const float*)d_in[1];
    const float* pp   = (const float*)d_in[2];
    const int Cc = in_sizes[2];             // 512
    const int Bn = in_sizes[0] / Cc;        // 65536

    bl_zero_kernel<<<1, CCOLS>>>();
    bl_pass1_kernel<<<296, 512>>>((const float4*)pred, (const float4*)targ, Bn);
    bl_finalize_kernel<<<1, CCOLS>>>(pp, (float*)d_out, Bn);
}

// round 6
// speedup vs baseline: 1.8380x; 1.8380x over previous
#include <cuda_runtime.h>

// BalancedLoss, fully fused single kernel.
// loss = mean( BCEWithLogits(pred,target) * w[t,c] ) with per-column weights
// derived from column positive-counts. Decomposition per column c:
//   A_c = sum (1-t)*softplus(x),  B_c = sum t*(softplus(x)-x),  P_c = sum t
//   loss = sum_c (w0_c*A_c + w1_c*B_c) / (B*C)
// One streaming pass (256 MB), block-level partial reduction, global atomics,
// last block finalizes + resets state (deterministic across graph replays).

#define CCOLS 512
#define C4 128          // float4 groups per row
#define NBLK 296        // 2 CTAs per SM on 148 SMs
#define NTHR 512        // 4 row-lanes of 128 threads

__device__ float g_accA[CCOLS];
__device__ float g_accB[CCOLS];
__device__ float g_accP[CCOLS];
__device__ unsigned int g_done;   // zero-init; reset by last block each run

__device__ __forceinline__ float softplus_f(float x) {
    return fmaxf(x, 0.0f) + __logf(1.0f + __expf(-fabsf(x)));
}

struct Acc {
    float a0, a1, a2, a3;
    float b0, b1, b2, b3;
    float p0, p1, p2, p3;
};

__device__ __forceinline__ void bl_acc(Acc& ac, const float4& x, const float4& t) {
    float s;
    s = softplus_f(x.x); ac.a0 += s - s*t.x; ac.b0 += (s - x.x)*t.x; ac.p0 += t.x;
    s = softplus_f(x.y); ac.a1 += s - s*t.y; ac.b1 += (s - x.y)*t.y; ac.p1 += t.y;
    s = softplus_f(x.z); ac.a2 += s - s*t.z; ac.b2 += (s - x.z)*t.z; ac.p2 += t.z;
    s = softplus_f(x.w); ac.a3 += s - s*t.w; ac.b3 += (s - x.w)*t.w; ac.p3 += t.w;
}

__global__ __launch_bounds__(NTHR, 2)
void bl_fused_kernel(const float4* __restrict__ pred,
                     const float4* __restrict__ targ,
                     const float* __restrict__ pos_prop,
                     float* __restrict__ out,
                     int Bn) {
    const int tid   = threadIdx.x;
    const int cg    = tid & (C4 - 1);    // column group (cols 4cg..4cg+3)
    const int rlane = tid >> 7;          // 0..3
    const int step  = gridDim.x * 4;     // row stride (1184)

    Acc ac = {0.f,0.f,0.f,0.f, 0.f,0.f,0.f,0.f, 0.f,0.f,0.f,0.f};

    int r = blockIdx.x * 4 + rlane;

    // Main loop: 4 row-steps per trip, loads front-batched for MLP=8.
    for (; r + 3 * step < Bn; r += 4 * step) {
        const long i0 = (long)r * C4 + cg;
        const long i1 = i0 + (long)step * C4;
        const long i2 = i1 + (long)step * C4;
        const long i3 = i2 + (long)step * C4;
        const float4 x0 = __ldcs(pred + i0);
        const float4 t0 = __ldcs(targ + i0);
        const float4 x1 = __ldcs(pred + i1);
        const float4 t1 = __ldcs(targ + i1);
        const float4 x2 = __ldcs(pred + i2);
        const float4 t2 = __ldcs(targ + i2);
        const float4 x3 = __ldcs(pred + i3);
        const float4 t3 = __ldcs(targ + i3);
        bl_acc(ac, x0, t0);
        bl_acc(ac, x1, t1);
        bl_acc(ac, x2, t2);
        bl_acc(ac, x3, t3);
    }
    // Remainder (<= 3 row-steps)
    for (; r < Bn; r += step) {
        const long i = (long)r * C4 + cg;
        const float4 x = __ldcs(pred + i);
        const float4 t = __ldcs(targ + i);
        bl_acc(ac, x, t);
    }

    // ---- intra-block reduction over the 4 row-lanes (shared, 3 rounds) ----
    __shared__ float4 sbuf[NTHR];   // 8 KB

    sbuf[tid] = make_float4(ac.a0, ac.a1, ac.a2, ac.a3);
    __syncthreads();
    if (rlane == 0) {
        float4 u = sbuf[tid + 128], v = sbuf[tid + 256], w = sbuf[tid + 384];
        ac.a0 += u.x + v.x + w.x;  ac.a1 += u.y + v.y + w.y;
        ac.a2 += u.z + v.z + w.z;  ac.a3 += u.w + v.w + w.w;
    }
    __syncthreads();
    sbuf[tid] = make_float4(ac.b0, ac.b1, ac.b2, ac.b3);
    __syncthreads();
    if (rlane == 0) {
        float4 u = sbuf[tid + 128], v = sbuf[tid + 256], w = sbuf[tid + 384];
        ac.b0 += u.x + v.x + w.x;  ac.b1 += u.y + v.y + w.y;
        ac.b2 += u.z + v.z + w.z;  ac.b3 += u.w + v.w + w.w;
    }
    __syncthreads();
    sbuf[tid] = make_float4(ac.p0, ac.p1, ac.p2, ac.p3);
    __syncthreads();
    if (rlane == 0) {
        float4 u = sbuf[tid + 128], v = sbuf[tid + 256], w = sbuf[tid + 384];
        ac.p0 += u.x + v.x + w.x;  ac.p1 += u.y + v.y + w.y;
        ac.p2 += u.z + v.z + w.z;  ac.p3 += u.w + v.w + w.w;

        const int c = cg * 4;
        atomicAdd(&g_accA[c + 0], ac.a0); atomicAdd(&g_accA[c + 1], ac.a1);
        atomicAdd(&g_accA[c + 2], ac.a2); atomicAdd(&g_accA[c + 3], ac.a3);
        atomicAdd(&g_accB[c + 0], ac.b0); atomicAdd(&g_accB[c + 1], ac.b1);
        atomicAdd(&g_accB[c + 2], ac.b2); atomicAdd(&g_accB[c + 3], ac.b3);
        atomicAdd(&g_accP[c + 0], ac.p0); atomicAdd(&g_accP[c + 1], ac.p1);
        atomicAdd(&g_accP[c + 2], ac.p2); atomicAdd(&g_accP[c + 3], ac.p3);
    }

    // ---- last-block finalize ----
    __shared__ bool s_last;
    __threadfence();
    __syncthreads();
    if (tid == 0) {
        unsigned int prev = atomicAdd(&g_done, 1u);
        s_last = (prev == gridDim.x - 1);
    }
    __syncthreads();
    if (!s_last) return;

    // This block observes all atomics (fence on producers + acquire via atomic).
    __threadfence();
    {
        const int c = tid;                  // 512 threads == 512 columns
        const float Bf = (float)Bn;
        const float P  = g_accP[c];
        const float bn = pos_prop[c] * Bf;

        const bool  majIs1 = (P >= bn);
        const float n_maj  = majIs1 ? P : (Bf - P);
        const float n_min  = Bf - n_maj;
        const float w_maj  = bn / n_maj;
        const float w_min  = (n_min > 0.0f) ? (Bf - bn) / fmaxf(n_min, 1.0f)
                                            : 1.0f;
        const float w1 = majIs1 ? w_maj : w_min;
        const float w0 = majIs1 ? w_min : w_maj;

        float contrib = w0 * g_accA[c] + w1 * g_accB[c];

        // reset state for next graph replay (deterministic)
        g_accA[c] = 0.0f;
        g_accB[c] = 0.0f;
        g_accP[c] = 0.0f;
        if (c == 0) g_done = 0u;

        __shared__ float sh[CCOLS];
        sh[c] = contrib;
        __syncthreads();
        #pragma unroll
        for (int s = CCOLS / 2; s > 0; s >>= 1) {
            if (c < s) sh[c] += sh[c + s];
            __syncthreads();
        }
        if (c == 0) out[0] = sh[0] / (Bf * (float)CCOLS);
    }
}

extern "C" void kernel_launch(void* const* d_in, const int* in_sizes, int n_in,
                              void* d_out, int out_size) {
    const float* pred = (const float*)d_in[0];
    const float* targ = (const float*)d_in[1];
    const float* pp   = (const float*)d_in[2];
    const int Cc = in_sizes[2];          // 512
    const int Bn = in_sizes[0] / Cc;     // 65536

    bl_fused_kernel<<<NBLK, NTHR>>>((const float4*)pred, (const float4*)targ,
                                    pp, (float*)d_out, Bn);
}